// round 1
// baseline (speedup 1.0000x reference)
#include <cuda_runtime.h>
#include <math.h>

#define B_SZ    2
#define SEQ     2048
#define DMODEL  1024
#define DINNER  2048
#define DSTATE  16
#define DCONV   4
#define DTRANK  64
#define ROWS    (B_SZ * SEQ)            // 4096
#define XZCOLS  (2 * DINNER)            // 4096
#define XDBLCOLS (DTRANK + 2 * DSTATE)  // 96

// ---------------- scratch (allocation-free) ----------------
__device__ float g_xz[ROWS * XZCOLS];       // 64 MB: [x_path | z]
__device__ float g_xconv[ROWS * DINNER];    // 32 MB
__device__ float g_xdbl[ROWS * XDBLCOLS];   // 1.5 MB: [dt_low | B | C]
__device__ float g_dt[ROWS * DINNER];       // 32 MB
__device__ float g_y[ROWS * DINNER];        // 32 MB

// ---------------- generic fp32 GEMM: C[M,N] = A[M,K] * B[N,K]^T ----------------
// BM=128, BN=128, BK=8, 256 threads, 8x8 per thread.
// Requires: M % 128 == 0, K % 8 == 0, lda/ldb multiples of 4. N arbitrary (guarded).
// act: 0 = none, 1 = softplus(v + bias[col])
__global__ void __launch_bounds__(256)
sgemm_abt(const float* __restrict__ A, int lda,
          const float* __restrict__ B, int ldb,
          float* __restrict__ C, int ldc,
          int M, int N, int K,
          const float* __restrict__ bias, int act)
{
    constexpr int BM = 128, BN = 128, BK = 8;
    __shared__ float As[BK][BM];
    __shared__ float Bs[BK][BN];

    const int tid = threadIdx.x;
    const int br = blockIdx.y * BM;
    const int bc = blockIdx.x * BN;
    const int tr = (tid >> 4) << 3;   // row of micro-tile within block tile
    const int tc = (tid & 15) << 3;   // col

    const int ldRow = tid >> 1;          // 0..127
    const int ldCol = (tid & 1) << 2;    // 0 or 4

    const float* Ap = A + (size_t)(br + ldRow) * lda + ldCol;
    const bool bok = (bc + ldRow) < N;
    const float* Bp = B + (size_t)(bc + ldRow) * ldb + ldCol;

    float acc[8][8];
    #pragma unroll
    for (int i = 0; i < 8; i++)
        #pragma unroll
        for (int j = 0; j < 8; j++) acc[i][j] = 0.f;

    for (int k0 = 0; k0 < K; k0 += BK) {
        float4 av = *reinterpret_cast<const float4*>(Ap + k0);
        float4 bv = bok ? *reinterpret_cast<const float4*>(Bp + k0)
                        : make_float4(0.f, 0.f, 0.f, 0.f);
        As[ldCol + 0][ldRow] = av.x;
        As[ldCol + 1][ldRow] = av.y;
        As[ldCol + 2][ldRow] = av.z;
        As[ldCol + 3][ldRow] = av.w;
        Bs[ldCol + 0][ldRow] = bv.x;
        Bs[ldCol + 1][ldRow] = bv.y;
        Bs[ldCol + 2][ldRow] = bv.z;
        Bs[ldCol + 3][ldRow] = bv.w;
        __syncthreads();

        #pragma unroll
        for (int kk = 0; kk < BK; kk++) {
            float4 a0 = *reinterpret_cast<const float4*>(&As[kk][tr]);
            float4 a1 = *reinterpret_cast<const float4*>(&As[kk][tr + 4]);
            float4 b0 = *reinterpret_cast<const float4*>(&Bs[kk][tc]);
            float4 b1 = *reinterpret_cast<const float4*>(&Bs[kk][tc + 4]);
            float ra[8] = {a0.x, a0.y, a0.z, a0.w, a1.x, a1.y, a1.z, a1.w};
            float rb[8] = {b0.x, b0.y, b0.z, b0.w, b1.x, b1.y, b1.z, b1.w};
            #pragma unroll
            for (int i = 0; i < 8; i++)
                #pragma unroll
                for (int j = 0; j < 8; j++)
                    acc[i][j] = fmaf(ra[i], rb[j], acc[i][j]);
        }
        __syncthreads();
    }

    #pragma unroll
    for (int i = 0; i < 8; i++) {
        int row = br + tr + i;
        float* Crow = C + (size_t)row * ldc;
        #pragma unroll
        for (int j = 0; j < 8; j++) {
            int col = bc + tc + j;
            if (col < N) {
                float v = acc[i][j];
                if (act == 1) {
                    v += bias[col];
                    v = (v > 20.f) ? v : log1pf(expf(v));
                }
                Crow[col] = v;
            }
        }
    }
}

// ---------------- causal depthwise conv (K=4) + silu ----------------
__global__ void conv_silu_kernel(const float* __restrict__ conv_w,
                                 const float* __restrict__ conv_b)
{
    int idx = blockIdx.x * blockDim.x + threadIdx.x;
    if (idx >= ROWS * DINNER) return;
    int row = idx >> 11;        // / DINNER
    int d   = idx & (DINNER - 1);
    int t   = row & (SEQ - 1);  // row % SEQ (SEQ = 2048)

    const float* cw = conv_w + d * DCONV;
    float acc = conv_b[d];
    #pragma unroll
    for (int k = 0; k < DCONV; k++) {
        int tt = t - (DCONV - 1) + k;
        if (tt >= 0)
            acc = fmaf(g_xz[(size_t)(row - (DCONV - 1) + k) * XZCOLS + d], cw[k], acc);
    }
    float s = acc / (1.f + __expf(-acc));   // silu
    g_xconv[idx] = s;
}

// ---------------- selective scan + gating epilogue ----------------
// One 16-lane group per channel (b,d); lane n owns state n. 4096 channels,
// 16 channels per 256-thread block -> 256 blocks.
__global__ void __launch_bounds__(256)
scan_kernel(const float* __restrict__ A_log, const float* __restrict__ Dp)
{
    const int tid  = threadIdx.x;
    const int lane = tid & 31;
    const int n    = lane & 15;
    const int chan = blockIdx.x * 16 + (tid >> 4);   // 0..4095
    const int b = chan >> 11;          // / DINNER
    const int d = chan & (DINNER - 1);

    const float A  = -expf(A_log[d * DSTATE + n]);
    const float Dd = Dp[d];

    const float* dt_p = g_dt    + (size_t)b * SEQ * DINNER + d;
    const float* u_p  = g_xconv + (size_t)b * SEQ * DINNER + d;
    const float* bc_p = g_xdbl  + (size_t)b * SEQ * XDBLCOLS + DTRANK + n;
    const float* z_p  = g_xz    + (size_t)b * SEQ * XZCOLS + DINNER + d;
    float*       y_p  = g_y     + (size_t)b * SEQ * DINNER + d;

    float h = 0.f;
    for (int t = 0; t < SEQ; t++) {
        float dtv = dt_p[(size_t)t * DINNER];
        float u   = u_p[(size_t)t * DINNER];
        float Bv  = bc_p[(size_t)t * XDBLCOLS];
        float Cv  = bc_p[(size_t)t * XDBLCOLS + DSTATE];

        float dA = expf(dtv * A);                 // accurate: errors compound over the scan
        h = fmaf(dA, h, dtv * Bv * u);
        float yv = Cv * h;

        yv += __shfl_xor_sync(0xffffffffu, yv, 8);
        yv += __shfl_xor_sync(0xffffffffu, yv, 4);
        yv += __shfl_xor_sync(0xffffffffu, yv, 2);
        yv += __shfl_xor_sync(0xffffffffu, yv, 1);

        if (n == 0) {
            float z  = z_p[(size_t)t * XZCOLS];
            float sz = z / (1.f + __expf(-z));    // silu(z)
            y_p[(size_t)t * DINNER] = (yv + u * Dd) * sz;
        }
    }
}

// ---------------- launch ----------------
extern "C" void kernel_launch(void* const* d_in, const int* in_sizes, int n_in,
                              void* d_out, int out_size)
{
    const float* x          = (const float*)d_in[0];
    const float* in_proj_w  = (const float*)d_in[1];
    const float* conv_w     = (const float*)d_in[2];
    const float* conv_b     = (const float*)d_in[3];
    const float* x_proj_w   = (const float*)d_in[4];
    const float* dt_proj_w  = (const float*)d_in[5];
    const float* dt_proj_b  = (const float*)d_in[6];
    const float* A_log      = (const float*)d_in[7];
    const float* D_param    = (const float*)d_in[8];
    const float* out_proj_w = (const float*)d_in[9];
    float* out = (float*)d_out;

    float *xz, *xconv, *xdbl, *dt, *y;
    cudaGetSymbolAddress((void**)&xz,    g_xz);
    cudaGetSymbolAddress((void**)&xconv, g_xconv);
    cudaGetSymbolAddress((void**)&xdbl,  g_xdbl);
    cudaGetSymbolAddress((void**)&dt,    g_dt);
    cudaGetSymbolAddress((void**)&y,     g_y);

    // 1) xz = x @ in_proj_w^T   (4096 x 4096, K=1024)
    {
        dim3 grid(XZCOLS / 128, ROWS / 128);
        sgemm_abt<<<grid, 256>>>(x, DMODEL, in_proj_w, DMODEL, xz, XZCOLS,
                                 ROWS, XZCOLS, DMODEL, nullptr, 0);
    }
    // 2) x_conv = silu(depthwise_conv(x_path) + b)
    {
        int total = ROWS * DINNER;
        conv_silu_kernel<<<(total + 255) / 256, 256>>>(conv_w, conv_b);
    }
    // 3) x_dbl = x_conv @ x_proj_w^T   (4096 x 96, K=2048)
    {
        dim3 grid((XDBLCOLS + 127) / 128, ROWS / 128);
        sgemm_abt<<<grid, 256>>>(xconv, DINNER, x_proj_w, DINNER, xdbl, XDBLCOLS,
                                 ROWS, XDBLCOLS, DINNER, nullptr, 0);
    }
    // 4) dt = softplus(x_dbl[:, :64] @ dt_proj_w^T + dt_proj_b)   (4096 x 2048, K=64)
    {
        dim3 grid(DINNER / 128, ROWS / 128);
        sgemm_abt<<<grid, 256>>>(xdbl, XDBLCOLS, dt_proj_w, DTRANK, dt, DINNER,
                                 ROWS, DINNER, DTRANK, dt_proj_b, 1);
    }
    // 5) selective scan + gating -> g_y
    scan_kernel<<<(B_SZ * DINNER) / 16, 256>>>(A_log, D_param);

    // 6) out = y @ out_proj_w^T   (4096 x 1024, K=2048)
    {
        dim3 grid(DMODEL / 128, ROWS / 128);
        sgemm_abt<<<grid, 256>>>(y, DINNER, out_proj_w, DINNER, out, DMODEL,
                                 ROWS, DMODEL, DINNER, nullptr, 0);
    }
}

// round 3
// speedup vs baseline: 1.3495x; 1.3495x over previous
#include <cuda_runtime.h>
#include <cuda_bf16.h>
#include <math.h>
#include <stdint.h>

#define B_SZ    2
#define SEQ     2048
#define DMODEL  1024
#define DINNER  2048
#define DSTATE  16
#define DCONV   4
#define DTRANK  64
#define ROWS    (B_SZ * SEQ)            // 4096
#define XZCOLS  (2 * DINNER)            // 4096
#define XDBLCOLS (DTRANK + 2 * DSTATE)  // 96

typedef __nv_bfloat16 bf16;

// ---------------- scratch (allocation-free) ----------------
__device__ float g_xz[ROWS * XZCOLS];
__device__ float g_xconv[ROWS * DINNER];
__device__ bf16  g_xconv_hi[ROWS * DINNER];
__device__ bf16  g_xconv_lo[ROWS * DINNER];
__device__ float g_xdbl[ROWS * XDBLCOLS];
__device__ bf16  g_xdbl_hi[ROWS * XDBLCOLS];
__device__ bf16  g_xdbl_lo[ROWS * XDBLCOLS];
__device__ float g_dt[ROWS * DINNER];
__device__ float g_y[ROWS * DINNER];
__device__ bf16  g_y_hi[ROWS * DINNER];
__device__ bf16  g_y_lo[ROWS * DINNER];
__device__ bf16  g_x_hi[ROWS * DMODEL];
__device__ bf16  g_x_lo[ROWS * DMODEL];
__device__ bf16  g_win_hi[XZCOLS * DMODEL];
__device__ bf16  g_win_lo[XZCOLS * DMODEL];
__device__ bf16  g_wxp_hi[XDBLCOLS * DINNER];
__device__ bf16  g_wxp_lo[XDBLCOLS * DINNER];
__device__ bf16  g_wdt_hi[DINNER * DTRANK];
__device__ bf16  g_wdt_lo[DINNER * DTRANK];
__device__ bf16  g_wout_hi[DMODEL * DINNER];
__device__ bf16  g_wout_lo[DMODEL * DINNER];

// ---------------- helpers ----------------
__device__ __forceinline__ uint32_t smem_u32(const void* p) {
    uint32_t a;
    asm("{ .reg .u64 t; cvta.to.shared.u64 t, %1; cvt.u32.u64 %0, t; }" : "=r"(a) : "l"(p));
    return a;
}
__device__ __forceinline__ void cp16(uint32_t dst, const void* src) {
    asm volatile("cp.async.cg.shared.global [%0], [%1], 16;" :: "r"(dst), "l"(src) : "memory");
}
__device__ __forceinline__ void ldm4(uint32_t* r, uint32_t addr) {
    asm volatile("ldmatrix.sync.aligned.m8n8.x4.shared.b16 {%0,%1,%2,%3}, [%4];"
                 : "=r"(r[0]), "=r"(r[1]), "=r"(r[2]), "=r"(r[3]) : "r"(addr));
}
__device__ __forceinline__ void mma16816(float* c, const uint32_t* a, uint32_t b0, uint32_t b1) {
    asm volatile("mma.sync.aligned.m16n8k16.row.col.f32.bf16.bf16.f32 "
                 "{%0,%1,%2,%3}, {%4,%5,%6,%7}, {%8,%9}, {%0,%1,%2,%3};"
                 : "+f"(c[0]), "+f"(c[1]), "+f"(c[2]), "+f"(c[3])
                 : "r"(a[0]), "r"(a[1]), "r"(a[2]), "r"(a[3]), "r"(b0), "r"(b1));
}
__device__ __forceinline__ void split2(float v, bf16& h, bf16& l) {
    h = __float2bfloat16(v);
    l = __float2bfloat16(v - __bfloat162float(h));
}

__global__ void split_kernel(const float* __restrict__ s, bf16* __restrict__ hi,
                             bf16* __restrict__ lo, int n) {
    int i = blockIdx.x * blockDim.x + threadIdx.x;
    if (i < n) {
        bf16 h, l;
        split2(s[i], h, l);
        hi[i] = h; lo[i] = l;
    }
}

// ---------------- mma.sync bf16-split GEMM: C[M,N] = A[M,K] * B[N,K]^T ----------------
// CTA tile 128x128, BK=32, double-buffered cp.async. 8 warps (4 m x 2 n), warp tile 32x64.
// C = Ah*Bh + Ah*Bl + Al*Bh  (fp32 accum). modes: 0 plain, 1 softplus(C+bias), 2 C + hi/lo split.
#define PITCH 80
#define TILE_BYTES (128 * PITCH)        // 10240
#define STAGE_BYTES (4 * TILE_BYTES)    // 40960
#define GEMM_SMEM (2 * STAGE_BYTES)     // 81920

__global__ void __launch_bounds__(256, 2)
gemm_bf16x3(const bf16* __restrict__ Ah, const bf16* __restrict__ Al, int lda,
            const bf16* __restrict__ Bh, const bf16* __restrict__ Bl, int ldb,
            float* __restrict__ C, bf16* __restrict__ Chi, bf16* __restrict__ Clo, int ldc,
            int N, int K, const float* __restrict__ bias, int mode)
{
    extern __shared__ char smem[];
    const uint32_t sb = smem_u32(smem);

    const int tid  = threadIdx.x;
    const int wid  = tid >> 5;
    const int lane = tid & 31;
    const int wm   = wid & 3;   // 0..3
    const int wn   = wid >> 2;  // 0..1
    const int m0 = blockIdx.y * 128;
    const int n0 = blockIdx.x * 128;

    float acc[2][8][4];
    #pragma unroll
    for (int i = 0; i < 2; i++)
        #pragma unroll
        for (int j = 0; j < 8; j++)
            #pragma unroll
            for (int k = 0; k < 4; k++) acc[i][j][k] = 0.f;

    const int nch = K >> 5;

    auto load_stage = [&](int c) {
        const int k0 = c << 5;
        const uint32_t buf = sb + (uint32_t)(c & 1) * STAGE_BYTES;
        #pragma unroll
        for (int t = 0; t < 2; t++) {
            int id = tid + (t << 8);          // 0..511
            int r  = id >> 2;
            int ch = id & 3;
            uint32_t doff = (uint32_t)(r * PITCH + ch * 16);
            size_t aoff = (size_t)(m0 + r) * lda + k0 + ch * 8;
            cp16(buf + doff,                  Ah + aoff);
            cp16(buf + TILE_BYTES + doff,     Al + aoff);
            int rb = n0 + r; if (rb > N - 1) rb = N - 1;
            size_t boff = (size_t)rb * ldb + k0 + ch * 8;
            cp16(buf + 2 * TILE_BYTES + doff, Bh + boff);
            cp16(buf + 3 * TILE_BYTES + doff, Bl + boff);
        }
        asm volatile("cp.async.commit_group;" ::: "memory");
    };

    auto compute_stage = [&](int c) {
        const uint32_t buf = sb + (uint32_t)(c & 1) * STAGE_BYTES;
        const uint32_t sAh = buf, sAl = buf + TILE_BYTES;
        const uint32_t sBh = buf + 2 * TILE_BYTES, sBl = buf + 3 * TILE_BYTES;
        #pragma unroll
        for (int ks = 0; ks < 2; ks++) {
            uint32_t ah[2][4], al[2][4];
            const int arow = wm * 32 + (lane & 15);
            const uint32_t aoff = (uint32_t)(ks * 32 + (lane >> 4) * 16);
            #pragma unroll
            for (int ma = 0; ma < 2; ma++) {
                ldm4(ah[ma], sAh + (uint32_t)((arow + ma * 16) * PITCH) + aoff);
                ldm4(al[ma], sAl + (uint32_t)((arow + ma * 16) * PITCH) + aoff);
            }
            #pragma unroll
            for (int ng = 0; ng < 2; ng++) {
                uint32_t bhf[2][4], blf[2][4];
                const int nrow = wn * 64 + ng * 32 + (lane & 7) + ((lane >> 4) & 1) * 8;
                const uint32_t boff = (uint32_t)(ks * 32 + ((lane >> 3) & 1) * 16);
                #pragma unroll
                for (int np = 0; np < 2; np++) {
                    ldm4(bhf[np], sBh + (uint32_t)((nrow + np * 16) * PITCH) + boff);
                    ldm4(blf[np], sBl + (uint32_t)((nrow + np * 16) * PITCH) + boff);
                }
                #pragma unroll
                for (int ma = 0; ma < 2; ma++)
                    #pragma unroll
                    for (int j = 0; j < 4; j++) {
                        float* cc = acc[ma][ng * 4 + j];
                        uint32_t h0 = bhf[j >> 1][(j & 1) * 2];
                        uint32_t h1 = bhf[j >> 1][(j & 1) * 2 + 1];
                        uint32_t l0 = blf[j >> 1][(j & 1) * 2];
                        uint32_t l1 = blf[j >> 1][(j & 1) * 2 + 1];
                        mma16816(cc, ah[ma], h0, h1);   // hh
                        mma16816(cc, ah[ma], l0, l1);   // hl
                        mma16816(cc, al[ma], h0, h1);   // lh
                    }
            }
        }
    };

    load_stage(0);
    for (int c = 0; c < nch; c++) {
        if (c + 1 < nch) {
            load_stage(c + 1);
            asm volatile("cp.async.wait_group 1;" ::: "memory");
        } else {
            asm volatile("cp.async.wait_group 0;" ::: "memory");
        }
        __syncthreads();
        compute_stage(c);
        __syncthreads();
    }

    // ---------------- epilogue ----------------
    const int rbase = m0 + wm * 32 + (lane >> 2);
    const int cbase = n0 + wn * 64 + (lane & 3) * 2;
    #pragma unroll
    for (int ma = 0; ma < 2; ma++) {
        #pragma unroll
        for (int na = 0; na < 8; na++) {
            int col = cbase + na * 8;
            if (col >= N) continue;
            #pragma unroll
            for (int half = 0; half < 2; half++) {
                int row = rbase + ma * 16 + half * 8;
                float v0 = acc[ma][na][half * 2];
                float v1 = acc[ma][na][half * 2 + 1];
                size_t o = (size_t)row * ldc + col;
                if (mode == 0) {
                    *reinterpret_cast<float2*>(C + o) = make_float2(v0, v1);
                } else if (mode == 1) {
                    v0 += bias[col];
                    v1 += bias[col + 1];
                    v0 = (v0 > 20.f) ? v0 : log1pf(expf(v0));
                    v1 = (v1 > 20.f) ? v1 : log1pf(expf(v1));
                    *reinterpret_cast<float2*>(C + o) = make_float2(v0, v1);
                } else {
                    *reinterpret_cast<float2*>(C + o) = make_float2(v0, v1);
                    bf16 h0, l0, h1, l1;
                    split2(v0, h0, l0);
                    split2(v1, h1, l1);
                    Chi[o] = h0; Chi[o + 1] = h1;
                    Clo[o] = l0; Clo[o + 1] = l1;
                }
            }
        }
    }
}

// ---------------- causal depthwise conv (K=4) + silu + split ----------------
__global__ void conv_silu_kernel(const float* __restrict__ conv_w,
                                 const float* __restrict__ conv_b)
{
    int idx = blockIdx.x * blockDim.x + threadIdx.x;
    if (idx >= ROWS * DINNER) return;
    int row = idx >> 11;
    int d   = idx & (DINNER - 1);
    int t   = row & (SEQ - 1);

    const float* cw = conv_w + d * DCONV;
    float acc = conv_b[d];
    #pragma unroll
    for (int k = 0; k < DCONV; k++) {
        int tt = t - (DCONV - 1) + k;
        if (tt >= 0)
            acc = fmaf(g_xz[(size_t)(row - (DCONV - 1) + k) * XZCOLS + d], cw[k], acc);
    }
    float s = acc / (1.f + __expf(-acc));
    g_xconv[idx] = s;
    bf16 h, l;
    split2(s, h, l);
    g_xconv_hi[idx] = h;
    g_xconv_lo[idx] = l;
}

// ---------------- selective scan + gating + split of y ----------------
__global__ void __launch_bounds__(256)
scan_kernel(const float* __restrict__ A_log, const float* __restrict__ Dp)
{
    const int tid  = threadIdx.x;
    const int lane = tid & 31;
    const int n    = lane & 15;
    const int chan = blockIdx.x * 16 + (tid >> 4);
    const int b = chan >> 11;
    const int d = chan & (DINNER - 1);

    const float A  = -expf(A_log[d * DSTATE + n]);
    const float Dd = Dp[d];

    const float* dt_p = g_dt    + (size_t)b * SEQ * DINNER + d;
    const float* u_p  = g_xconv + (size_t)b * SEQ * DINNER + d;
    const float* bc_p = g_xdbl  + (size_t)b * SEQ * XDBLCOLS + DTRANK + n;
    const float* z_p  = g_xz    + (size_t)b * SEQ * XZCOLS + DINNER + d;
    const size_t ybase = (size_t)b * SEQ * DINNER + d;

    float h = 0.f;
    for (int t = 0; t < SEQ; t++) {
        float dtv = dt_p[(size_t)t * DINNER];
        float u   = u_p[(size_t)t * DINNER];
        float Bv  = bc_p[(size_t)t * XDBLCOLS];
        float Cv  = bc_p[(size_t)t * XDBLCOLS + DSTATE];

        float dA = expf(dtv * A);
        h = fmaf(dA, h, dtv * Bv * u);
        float yv = Cv * h;

        yv += __shfl_xor_sync(0xffffffffu, yv, 8);
        yv += __shfl_xor_sync(0xffffffffu, yv, 4);
        yv += __shfl_xor_sync(0xffffffffu, yv, 2);
        yv += __shfl_xor_sync(0xffffffffu, yv, 1);

        if (n == 0) {
            float z  = z_p[(size_t)t * XZCOLS];
            float sz = z / (1.f + __expf(-z));
            float yo = (yv + u * Dd) * sz;
            size_t o = ybase + (size_t)t * DINNER;
            g_y[o] = yo;
            bf16 hh, ll;
            split2(yo, hh, ll);
            g_y_hi[o] = hh;
            g_y_lo[o] = ll;
        }
    }
}

// ---------------- launch ----------------
extern "C" void kernel_launch(void* const* d_in, const int* in_sizes, int n_in,
                              void* d_out, int out_size)
{
    const float* x          = (const float*)d_in[0];
    const float* in_proj_w  = (const float*)d_in[1];
    const float* conv_w     = (const float*)d_in[2];
    const float* conv_b     = (const float*)d_in[3];
    const float* x_proj_w   = (const float*)d_in[4];
    const float* dt_proj_w  = (const float*)d_in[5];
    const float* dt_proj_b  = (const float*)d_in[6];
    const float* A_log      = (const float*)d_in[7];
    const float* D_param    = (const float*)d_in[8];
    const float* out_proj_w = (const float*)d_in[9];
    float* out = (float*)d_out;

    float *xz, *xconv, *xdbl, *dt, *y;
    bf16 *xh, *xl, *winh, *winl, *wxph, *wxpl, *wdth, *wdtl, *wouth, *woutl;
    bf16 *xch, *xcl, *xdh, *xdl, *yh, *yl;
    cudaGetSymbolAddress((void**)&xz,    g_xz);
    cudaGetSymbolAddress((void**)&xconv, g_xconv);
    cudaGetSymbolAddress((void**)&xdbl,  g_xdbl);
    cudaGetSymbolAddress((void**)&dt,    g_dt);
    cudaGetSymbolAddress((void**)&y,     g_y);
    cudaGetSymbolAddress((void**)&xh,    g_x_hi);
    cudaGetSymbolAddress((void**)&xl,    g_x_lo);
    cudaGetSymbolAddress((void**)&winh,  g_win_hi);
    cudaGetSymbolAddress((void**)&winl,  g_win_lo);
    cudaGetSymbolAddress((void**)&wxph,  g_wxp_hi);
    cudaGetSymbolAddress((void**)&wxpl,  g_wxp_lo);
    cudaGetSymbolAddress((void**)&wdth,  g_wdt_hi);
    cudaGetSymbolAddress((void**)&wdtl,  g_wdt_lo);
    cudaGetSymbolAddress((void**)&wouth, g_wout_hi);
    cudaGetSymbolAddress((void**)&woutl, g_wout_lo);
    cudaGetSymbolAddress((void**)&xch,   g_xconv_hi);
    cudaGetSymbolAddress((void**)&xcl,   g_xconv_lo);
    cudaGetSymbolAddress((void**)&xdh,   g_xdbl_hi);
    cudaGetSymbolAddress((void**)&xdl,   g_xdbl_lo);
    cudaGetSymbolAddress((void**)&yh,    g_y_hi);
    cudaGetSymbolAddress((void**)&yl,    g_y_lo);

    cudaFuncSetAttribute(gemm_bf16x3, cudaFuncAttributeMaxDynamicSharedMemorySize, GEMM_SMEM);

    // splits of inputs / weights
    {
        int n1 = ROWS * DMODEL;
        split_kernel<<<(n1 + 255) / 256, 256>>>(x, xh, xl, n1);
        int n2 = XZCOLS * DMODEL;
        split_kernel<<<(n2 + 255) / 256, 256>>>(in_proj_w, winh, winl, n2);
        int n3 = XDBLCOLS * DINNER;
        split_kernel<<<(n3 + 255) / 256, 256>>>(x_proj_w, wxph, wxpl, n3);
        int n4 = DINNER * DTRANK;
        split_kernel<<<(n4 + 255) / 256, 256>>>(dt_proj_w, wdth, wdtl, n4);
        int n5 = DMODEL * DINNER;
        split_kernel<<<(n5 + 255) / 256, 256>>>(out_proj_w, wouth, woutl, n5);
    }

    // 1) xz = x @ in_proj_w^T   (4096 x 4096, K=1024)
    {
        dim3 grid(XZCOLS / 128, ROWS / 128);
        gemm_bf16x3<<<grid, 256, GEMM_SMEM>>>(xh, xl, DMODEL, winh, winl, DMODEL,
                                              xz, nullptr, nullptr, XZCOLS,
                                              XZCOLS, DMODEL, nullptr, 0);
    }
    // 2) conv + silu (+ split)
    {
        int total = ROWS * DINNER;
        conv_silu_kernel<<<(total + 255) / 256, 256>>>(conv_w, conv_b);
    }
    // 3) x_dbl = xconv @ x_proj_w^T  (4096 x 96, K=2048), fp32 + hi/lo
    {
        dim3 grid(1, ROWS / 128);
        gemm_bf16x3<<<grid, 256, GEMM_SMEM>>>(xch, xcl, DINNER, wxph, wxpl, DINNER,
                                              xdbl, xdh, xdl, XDBLCOLS,
                                              XDBLCOLS, DINNER, nullptr, 2);
    }
    // 4) dt = softplus(xdbl[:, :64] @ dt_proj_w^T + b)  (4096 x 2048, K=64)
    {
        dim3 grid(DINNER / 128, ROWS / 128);
        gemm_bf16x3<<<grid, 256, GEMM_SMEM>>>(xdh, xdl, XDBLCOLS, wdth, wdtl, DTRANK,
                                              dt, nullptr, nullptr, DINNER,
                                              DINNER, DTRANK, dt_proj_b, 1);
    }
    // 5) selective scan + gating (+ split of y)
    scan_kernel<<<(B_SZ * DINNER) / 16, 256>>>(A_log, D_param);

    // 6) out = y @ out_proj_w^T  (4096 x 1024, K=2048)
    {
        dim3 grid(DMODEL / 128, ROWS / 128);
        gemm_bf16x3<<<grid, 256, GEMM_SMEM>>>(yh, yl, DINNER, wouth, woutl, DINNER,
                                              out, nullptr, nullptr, DMODEL,
                                              DMODEL, DINNER, nullptr, 0);
    }
}